// round 7
// baseline (speedup 1.0000x reference)
#include <cuda_runtime.h>
#include <cstdint>

// ============================================================================
// 16-qubit statevector simulator, 64 batches, 3 layers (Rot x16 + CNOT chain).
// Round 7: batch-pair SoA. Each f32x2 lane = one batch of a batch pair.
//  * re/im in separate packed registers -> complex MAC is pure fma.rn.f32x2,
//    NO half-swaps, no cross-lane ops anywhere. SU(2) structure (u10=-u01*,
//    u11=u00*) -> 7 packed coefficients per gate.
//  * 128-bit (ulonglong2) global + smem ops: instruction counts halve.
//  * Same pass structure as R6: passA (qubits 4..15, 2 transposes),
//    passB (qubits 0..3, CNOT relabel in store address), passBmeas (parity).
// ============================================================================

#define THREADS   256
#define TILE      4096
#define PAD_SLOTS (TILE + (TILE >> 4))   // 4352, slot = t + (t>>4)

typedef unsigned long long ull;

__device__ ulonglong2 g_bufA[32 * 65536];   // 32 batch pairs
__device__ ulonglong2 g_bufB[32 * 65536];

// 7 packed coefficients per SU(2) gate: a=u00, b=u01 (row 0), duplicated lanes
struct G7 { ull ar, ai, nai, br, bi, nbr, nbi; };

struct Smem {
    ulonglong2 amp[PAD_SLOTS];
    G7 um[12];
};
#define SMEM_BYTES ((int)sizeof(Smem))

// ---------------- packed f32x2 primitives ----------------
__device__ __forceinline__ ull f2fma(ull a, ull b, ull c) {
    ull d; asm("fma.rn.f32x2 %0, %1, %2, %3;" : "=l"(d) : "l"(a), "l"(b), "l"(c));
    return d;
}
__device__ __forceinline__ ull f2mul(ull a, ull b) {
    ull d; asm("mul.rn.f32x2 %0, %1, %2;" : "=l"(d) : "l"(a), "l"(b));
    return d;
}
__device__ __forceinline__ ull f2add(ull a, ull b) {
    ull d; asm("add.rn.f32x2 %0, %1, %2;" : "=l"(d) : "l"(a), "l"(b));
    return d;
}
__device__ __forceinline__ ull f2sub(ull a, ull b) {
    ull d; asm("sub.rn.f32x2 %0, %1, %2;" : "=l"(d) : "l"(a), "l"(b));
    return d;
}
__device__ __forceinline__ ull pk(float lo, float hi) {
    ull r; asm("mov.b64 %0, {%1, %2};" : "=l"(r) : "f"(lo), "f"(hi));
    return r;
}
__device__ __forceinline__ void upk(ull v, float& lo, float& hi) {
    asm("mov.b64 {%0, %1}, %2;" : "=f"(lo), "=f"(hi) : "l"(v));
}

// U = Rz(tz)@Ry(ty)@Rx(tx) is SU(2): row0 = (u00, u01) determines all.
__device__ __forceinline__ void make_u(const float* __restrict__ vp, int layer, int q,
                                       G7* __restrict__ g) {
    const float* p = vp + ((layer * 16) + q) * 6;
    float tx = p[0], ty = p[1], tz = p[2];
    float cx = cosf(0.5f * tx), sx = sinf(0.5f * tx);
    float cy = cosf(0.5f * ty), sy = sinf(0.5f * ty);
    float cz = cosf(0.5f * tz), sz = sinf(0.5f * tz);
    float m00r =  cy * cx, m00i =  sy * sx;
    float m01r = -sy * cx, m01i = -cy * sx;
    float u0 = cz * m00r + sz * m00i, u1 = cz * m00i - sz * m00r;  // u00
    float u2 = cz * m01r + sz * m01i, u3 = cz * m01i - sz * m01r;  // u01
    g->ar  = pk(u0, u0);  g->ai  = pk(u1, u1);  g->nai = pk(-u1, -u1);
    g->br  = pk(u2, u2);  g->bi  = pk(u3, u3);
    g->nbr = pk(-u2, -u2); g->nbi = pk(-u3, -u3);
}

// SoA SU(2) pair gate: 16 FFMA2 for 2 amplitude pairs (2 batches), no swaps.
// na = u00*a + u01*b ; nb = -u01^* a + u00^* b
__device__ __forceinline__ void vgate(ull& rea, ull& ima, ull& reb, ull& imb,
                                      const G7& g) {
    ull nra = f2fma(g.ar,  rea, f2fma(g.nai, ima, f2fma(g.br,  reb, f2mul(g.nbi, imb))));
    ull nia = f2fma(g.ai,  rea, f2fma(g.ar,  ima, f2fma(g.bi,  reb, f2mul(g.br,  imb))));
    ull nrb = f2fma(g.nbr, rea, f2fma(g.nbi, ima, f2fma(g.ar,  reb, f2mul(g.ai,  imb))));
    ull nib = f2fma(g.bi,  rea, f2fma(g.nbr, ima, f2fma(g.nai, reb, f2mul(g.ar,  imb))));
    rea = nra; ima = nia; reb = nrb; imb = nib;
}

// apply gates um[b0+k] on register bit k, k=0..3
__device__ __forceinline__ void gate4v(ull* __restrict__ rev, ull* __restrict__ imv,
                                       const G7* __restrict__ um, int b0) {
#pragma unroll
    for (int k = 0; k < 4; k++) {
        int s = 1 << k;
#pragma unroll
        for (int r0 = 0; r0 < 16; r0++) {
            if (r0 & s) continue;
            vgate(rev[r0], imv[r0], rev[r0 | s], imv[r0 | s], um[b0 + k]);
        }
    }
}

// ---------------------------------------------------------------------------
// Pass A: tile = bits [11:0], blockIdx = pair(5b)<<4 | tile(4b).
// permLoad applies prev-layer CNOTs q=4..14: a = i ^ ((i>>1) & 0x7FF).
// m1: t=(r<<8)|tid   m2: t=(tid<<4)|r   m3: t=((tid>>4)<<8)|(r<<4)|(tid&15)
// ---------------------------------------------------------------------------
__global__ void __launch_bounds__(THREADS, 2)
passA(const float* __restrict__ sr, const float* __restrict__ si,
      const ulonglong2* __restrict__ src, ulonglong2* __restrict__ dst,
      const float* __restrict__ vp, int layer, int permLoad, int fromInput) {
    extern __shared__ char smraw[];
    Smem* sm = (Smem*)smraw;
    int tid = threadIdx.x;
    int pair = blockIdx.x >> 4, tile = blockIdx.x & 15;
    int base  = pair << 16;
    int tbase = tile << 12;

    if (tid < 12) make_u(vp, layer, 15 - tid, &sm->um[tid]);  // um[b]: tile bit b
    __syncthreads();

    ull rev[16], imv[16];

    if (fromInput) {
        const float* sr0 = sr + (pair * 2) * 65536;
        const float* si0 = si + (pair * 2) * 65536;
#pragma unroll
        for (int r = 0; r < 16; r++) {
            int i = tbase | (r << 8) | tid;
            rev[r] = pk(sr0[i], sr0[i + 65536]);
            imv[r] = pk(si0[i], si0[i + 65536]);
        }
    } else if (permLoad) {
#pragma unroll
        for (int r = 0; r < 16; r++) {
            int i = tbase | (r << 8) | tid;
            int a = i ^ ((i >> 1) & 0x7FF);   // inverse of CNOT chain q=4..14
            ulonglong2 v = src[base + a];
            rev[r] = v.x; imv[r] = v.y;
        }
    } else {
#pragma unroll
        for (int r = 0; r < 16; r++) {
            ulonglong2 v = src[base + (tbase | (r << 8) | tid)];
            rev[r] = v.x; imv[r] = v.y;
        }
    }

    // gates on m1 reg bits t[11:8] (qubits 7..4)
    gate4v(rev, imv, sm->um, 8);

    // transpose m1 -> m2
#pragma unroll
    for (int r = 0; r < 16; r++) {
        int t = (r << 8) | tid;
        sm->amp[t + (t >> 4)] = make_ulonglong2(rev[r], imv[r]);
    }
    __syncthreads();
#pragma unroll
    for (int r = 0; r < 16; r++) {
        int t = (tid << 4) | r;
        ulonglong2 v = sm->amp[t + (t >> 4)];
        rev[r] = v.x; imv[r] = v.y;
    }

    // gates on m2 reg bits t[3:0] (qubits 15..12)
    gate4v(rev, imv, sm->um, 0);

    // transpose m2 -> m3
    __syncthreads();
#pragma unroll
    for (int r = 0; r < 16; r++) {
        int t = (tid << 4) | r;
        sm->amp[t + (t >> 4)] = make_ulonglong2(rev[r], imv[r]);
    }
    __syncthreads();
#pragma unroll
    for (int r = 0; r < 16; r++) {
        int t = ((tid >> 4) << 8) | (r << 4) | (tid & 15);
        ulonglong2 v = sm->amp[t + (t >> 4)];
        rev[r] = v.x; imv[r] = v.y;
    }

    // gates on m3 reg bits t[7:4] (qubits 11..8)
    gate4v(rev, imv, sm->um, 4);

    // store from m3
#pragma unroll
    for (int r = 0; r < 16; r++) {
        int t = ((tid >> 4) << 8) | (r << 4) | (tid & 15);
        dst[base + (tbase | t)] = make_ulonglong2(rev[r], imv[r]);
    }
}

// ---------------------------------------------------------------------------
// Pass B: t=(r<<8)|tid, g = (t[11:7]<<11)|(m<<7)|t[6:0]. Reg bits = g[15:12]
// = qubits 3..0. CNOT q=0..3 relabel = suffix-XOR on g[15:11] in store addr.
// ---------------------------------------------------------------------------
__global__ void __launch_bounds__(THREADS, 2)
passB(const ulonglong2* __restrict__ src, ulonglong2* __restrict__ dst,
      const float* __restrict__ vp, int layer) {
    __shared__ G7 um[4];
    int tid = threadIdx.x;
    int pair = blockIdx.x >> 4, m = blockIdx.x & 15;
    int base = pair << 16;

    if (tid < 4) make_u(vp, layer, 3 - tid, &um[tid]);  // um[k]: qubit 3-k (reg bit k)
    __syncthreads();

    ull rev[16], imv[16];
#pragma unroll
    for (int r = 0; r < 16; r++) {
        int t = (r << 8) | tid;
        int g = ((t >> 7) << 11) | (m << 7) | (t & 0x7F);
        ulonglong2 v = src[base + g];
        rev[r] = v.x; imv[r] = v.y;
    }

    gate4v(rev, imv, um, 0);

#pragma unroll
    for (int r = 0; r < 16; r++) {
        int t = (r << 8) | tid;
        int h = t >> 7;                      // 5 bits = g[15:11]
        h ^= h >> 1; h ^= h >> 2; h ^= h >> 4;
        int gp = (h << 11) | (m << 7) | (t & 0x7F);
        dst[base + gp] = make_ulonglong2(rev[r], imv[r]);
    }
}

// ---------------------------------------------------------------------------
// Pass B measure: gates qubits 0..3, fold final CNOT chain into parity,
// reduce Z expectations per batch lane, apply linear head.
// ---------------------------------------------------------------------------
__global__ void __launch_bounds__(THREADS, 2)
passBmeas(const ulonglong2* __restrict__ src, const float* __restrict__ vp,
          const float* __restrict__ hw, float* __restrict__ out, int layer) {
    __shared__ G7 um[4];
    __shared__ float feats[2][16];
    int tid = threadIdx.x;
    int l = tid & 31;
    int pair = blockIdx.x >> 4, m = blockIdx.x & 15;
    int base = pair << 16;

    if (tid < 4) make_u(vp, layer, 3 - tid, &um[tid]);
    if (tid < 32) feats[tid >> 4][tid & 15] = 0.0f;
    __syncthreads();

    ull rev[16], imv[16];
#pragma unroll
    for (int r = 0; r < 16; r++) {
        int t = (r << 8) | tid;
        int g = ((t >> 7) << 11) | (m << 7) | (t & 0x7F);
        ulonglong2 v = src[base + g];
        rev[r] = v.x; imv[r] = v.y;
    }

    gate4v(rev, imv, um, 0);

    ull acc[16];
#pragma unroll
    for (int q = 0; q < 16; q++) acc[q] = pk(0.0f, 0.0f);
#pragma unroll
    for (int r = 0; r < 16; r++) {
        int t = (r << 8) | tid;
        int j = ((t >> 7) << 11) | (m << 7) | (t & 0x7F);
        ull p = f2fma(rev[r], rev[r], f2mul(imv[r], imv[r]));  // packed per-batch prob
        int f = j;                            // suffix-XOR parity
        f ^= f >> 1; f ^= f >> 2; f ^= f >> 4; f ^= f >> 8;
#pragma unroll
        for (int q = 0; q < 16; q++)
            acc[q] = ((f >> (15 - q)) & 1) ? f2sub(acc[q], p) : f2add(acc[q], p);
    }
#pragma unroll
    for (int q = 0; q < 16; q++) {
#pragma unroll
        for (int off = 16; off; off >>= 1)
            acc[q] = f2add(acc[q], __shfl_xor_sync(0xffffffffu, acc[q], off));
    }
    if (l == 0) {
#pragma unroll
        for (int q = 0; q < 16; q++) {
            float a0, a1; upk(acc[q], a0, a1);
            atomicAdd(&feats[0][q], a0);
            atomicAdd(&feats[1][q], a1);
        }
    }
    __syncthreads();
    if (tid == 0) {
        float v0 = 0.0f, v1 = 0.0f;
        for (int q = 0; q < 16; q++) {
            v0 += feats[0][q] * hw[q];
            v1 += feats[1][q] * hw[q];
        }
        atomicAdd(&out[pair * 2], v0);
        atomicAdd(&out[pair * 2 + 1], v1);
    }
}

__global__ void initOut(float* __restrict__ out, const float* __restrict__ hb) {
    if (threadIdx.x < 64) out[threadIdx.x] = hb[0];
}

extern "C" void kernel_launch(void* const* d_in, const int* in_sizes, int n_in,
                              void* d_out, int out_size) {
    const float* sr = (const float*)d_in[0];
    const float* si = (const float*)d_in[1];
    const float* vp = (const float*)d_in[2];
    const float* hw = (const float*)d_in[3];
    const float* hb = (const float*)d_in[4];
    float* out = (float*)d_out;

    cudaFuncSetAttribute(passA, cudaFuncAttributeMaxDynamicSharedMemorySize, SMEM_BYTES);

    ulonglong2 *b0, *b1;
    cudaGetSymbolAddress((void**)&b0, g_bufA);
    cudaGetSymbolAddress((void**)&b1, g_bufB);

    initOut<<<1, 64>>>(out, hb);
    // layer 0
    passA<<<512, THREADS, SMEM_BYTES>>>(sr, si, nullptr, b0, vp, 0, 0, 1);
    passB<<<512, THREADS>>>(b0, b1, vp, 0);
    // layer 1 (load applies layer-0 CNOT chain q=4..14)
    passA<<<512, THREADS, SMEM_BYTES>>>(nullptr, nullptr, b1, b0, vp, 1, 1, 0);
    passB<<<512, THREADS>>>(b0, b1, vp, 1);
    // layer 2
    passA<<<512, THREADS, SMEM_BYTES>>>(nullptr, nullptr, b1, b0, vp, 2, 1, 0);
    passBmeas<<<512, THREADS>>>(b0, vp, hw, out, 2);
}

// round 8
// speedup vs baseline: 1.0093x; 1.0093x over previous
#include <cuda_runtime.h>
#include <cstdint>

// ============================================================================
// 16-qubit statevector simulator, 64 batches, 3 layers (Rot x16 + CNOT chain).
// Round 8: batch-pair SoA (no swaps) + 8 slots/thread for high occupancy.
//  * re/im in separate f32x2 regs; SU(2) gate = 16 clean FFMA2 per pair
//    (2 batches), zero cross-lane/swap ops.
//  * passA: qubits 5..15 on tile bits [10:0]; groups r=t[10:8] -> t[2:0] ->
//    t[5:3] -> t[7:6], 3 padded-smem transposes (pad t+(t>>3), conflict-free).
//  * passB: qubits 0..4 on bits {15..11}+[5:0]; 1 transpose; CNOT q0..3
//    relabel = 5-bit suffix-XOR folded into store address.
//  * CNOT q=4..14 folded into next passA's load perm; full chain folded into
//    measurement parity (passBmeas).
// ============================================================================

#define THREADS   256
#define TILE      2048
#define PAD_SLOTS (TILE + (TILE >> 3))   // 2304, slot = t + (t>>3)

typedef unsigned long long ull;

__device__ ulonglong2 g_bufA[32 * 65536];   // 32 batch pairs x 2^16 (re2,im2)
__device__ ulonglong2 g_bufB[32 * 65536];

// 7 packed coefficients per SU(2) gate (row0 = u00,u01 determines all)
struct G7 { ull ar, ai, nai, br, bi, nbr, nbi; };

struct Smem {
    ulonglong2 amp[PAD_SLOTS];
    G7 um[11];
};
#define SMEM_BYTES ((int)sizeof(Smem))

// ---------------- packed f32x2 primitives ----------------
__device__ __forceinline__ ull f2fma(ull a, ull b, ull c) {
    ull d; asm("fma.rn.f32x2 %0, %1, %2, %3;" : "=l"(d) : "l"(a), "l"(b), "l"(c));
    return d;
}
__device__ __forceinline__ ull f2mul(ull a, ull b) {
    ull d; asm("mul.rn.f32x2 %0, %1, %2;" : "=l"(d) : "l"(a), "l"(b));
    return d;
}
__device__ __forceinline__ ull f2add(ull a, ull b) {
    ull d; asm("add.rn.f32x2 %0, %1, %2;" : "=l"(d) : "l"(a), "l"(b));
    return d;
}
__device__ __forceinline__ ull f2sub(ull a, ull b) {
    ull d; asm("sub.rn.f32x2 %0, %1, %2;" : "=l"(d) : "l"(a), "l"(b));
    return d;
}
__device__ __forceinline__ ull pk(float lo, float hi) {
    ull r; asm("mov.b64 %0, {%1, %2};" : "=l"(r) : "f"(lo), "f"(hi));
    return r;
}
__device__ __forceinline__ void upk(ull v, float& lo, float& hi) {
    asm("mov.b64 {%0, %1}, %2;" : "=f"(lo), "=f"(hi) : "l"(v));
}

// U = Rz(tz)@Ry(ty)@Rx(tx) is SU(2): row0 = (u00, u01) determines all.
__device__ __forceinline__ void make_u(const float* __restrict__ vp, int layer, int q,
                                       G7* __restrict__ g) {
    const float* p = vp + ((layer * 16) + q) * 6;
    float tx = p[0], ty = p[1], tz = p[2];
    float cx = cosf(0.5f * tx), sx = sinf(0.5f * tx);
    float cy = cosf(0.5f * ty), sy = sinf(0.5f * ty);
    float cz = cosf(0.5f * tz), sz = sinf(0.5f * tz);
    float m00r =  cy * cx, m00i =  sy * sx;
    float m01r = -sy * cx, m01i = -cy * sx;
    float u0 = cz * m00r + sz * m00i, u1 = cz * m00i - sz * m00r;  // u00
    float u2 = cz * m01r + sz * m01i, u3 = cz * m01i - sz * m01r;  // u01
    g->ar  = pk(u0, u0);  g->ai  = pk(u1, u1);  g->nai = pk(-u1, -u1);
    g->br  = pk(u2, u2);  g->bi  = pk(u3, u3);
    g->nbr = pk(-u2, -u2); g->nbi = pk(-u3, -u3);
}

// SoA SU(2) pair gate: 16 FFMA2 for one amplitude pair x 2 batches, no swaps.
// na = u00*a + u01*b ; nb = -u01^* a + u00^* b
__device__ __forceinline__ void vgate(ull& rea, ull& ima, ull& reb, ull& imb,
                                      const G7& g) {
    ull nra = f2fma(g.ar,  rea, f2fma(g.nai, ima, f2fma(g.br,  reb, f2mul(g.nbi, imb))));
    ull nia = f2fma(g.ai,  rea, f2fma(g.ar,  ima, f2fma(g.bi,  reb, f2mul(g.br,  imb))));
    ull nrb = f2fma(g.nbr, rea, f2fma(g.nbi, ima, f2fma(g.ar,  reb, f2mul(g.ai,  imb))));
    ull nib = f2fma(g.bi,  rea, f2fma(g.nbr, ima, f2fma(g.nai, reb, f2mul(g.ar,  imb))));
    rea = nra; ima = nia; reb = nrb; imb = nib;
}

// one gate level on register bit log2(s) of 8 slots
__device__ __forceinline__ void level(ull* __restrict__ rev, ull* __restrict__ imv,
                                      const G7& gsm, int s) {
    G7 g = gsm;   // pull coeffs into registers once
#pragma unroll
    for (int r0 = 0; r0 < 8; r0++) {
        if (r0 & s) continue;
        vgate(rev[r0], imv[r0], rev[r0 | s], imv[r0 | s], g);
    }
}

// ---------------------------------------------------------------------------
// Pass A: tile = bits [10:0] (2048 amps), tile id = bits [15:11].
// blockIdx = pair(5b)<<5 | tile(5b).
// permLoad applies prev-layer CNOTs q=4..14: a = i ^ ((i>>1) & 0x7FF)
// (controls may be tile-id bits; result stays in-tile since mask <= 0x7FF).
// m1: t=(r<<8)|tid                  gates bits 10,9,8  (qubits 5,6,7)
// m2: t=(tid<<3)|r                  gates bits 2,1,0   (qubits 13,14,15)
// m3: t=((tid>>3)<<6)|(r<<3)|(tid&7) gates bits 5,4,3  (qubits 10,11,12)
// m4: t=((tid>>5)<<8)|(r<<5)|(tid&31) gates bits 7,6   (qubits 8,9)
// um[b] = gate on tile bit b = qubit 15-b, b=0..10.
// ---------------------------------------------------------------------------
__global__ void __launch_bounds__(THREADS, 3)
passA(const float* __restrict__ sr, const float* __restrict__ si,
      const ulonglong2* __restrict__ src, ulonglong2* __restrict__ dst,
      const float* __restrict__ vp, int layer, int permLoad, int fromInput) {
    extern __shared__ char smraw[];
    Smem* sm = (Smem*)smraw;
    int tid = threadIdx.x;
    int pair = blockIdx.x >> 5, tile = blockIdx.x & 31;
    int base  = pair << 16;
    int tbase = tile << 11;

    if (tid < 11) make_u(vp, layer, 15 - tid, &sm->um[tid]);
    __syncthreads();

    ull rev[8], imv[8];

    // ---- load in m1 ----
    if (fromInput) {
        const float* sr0 = sr + (pair * 2) * 65536;
        const float* si0 = si + (pair * 2) * 65536;
#pragma unroll
        for (int r = 0; r < 8; r++) {
            int i = tbase | (r << 8) | tid;
            rev[r] = pk(sr0[i], sr0[i + 65536]);
            imv[r] = pk(si0[i], si0[i + 65536]);
        }
    } else if (permLoad) {
#pragma unroll
        for (int r = 0; r < 8; r++) {
            int i = tbase | (r << 8) | tid;
            int a = i ^ ((i >> 1) & 0x7FF);   // inverse of CNOT chain q=4..14
            ulonglong2 v = src[base + a];
            rev[r] = v.x; imv[r] = v.y;
        }
    } else {
#pragma unroll
        for (int r = 0; r < 8; r++) {
            ulonglong2 v = src[base + (tbase | (r << 8) | tid)];
            rev[r] = v.x; imv[r] = v.y;
        }
    }

    // gates m1: bits 8,9,10
    level(rev, imv, sm->um[8], 1);
    level(rev, imv, sm->um[9], 2);
    level(rev, imv, sm->um[10], 4);

    // transpose m1 -> m2
#pragma unroll
    for (int r = 0; r < 8; r++) {
        int t = (r << 8) | tid;
        sm->amp[t + (t >> 3)] = make_ulonglong2(rev[r], imv[r]);
    }
    __syncthreads();
#pragma unroll
    for (int r = 0; r < 8; r++) {
        int t = (tid << 3) | r;
        ulonglong2 v = sm->amp[t + (t >> 3)];
        rev[r] = v.x; imv[r] = v.y;
    }

    // gates m2: bits 0,1,2
    level(rev, imv, sm->um[0], 1);
    level(rev, imv, sm->um[1], 2);
    level(rev, imv, sm->um[2], 4);

    // transpose m2 -> m3
    __syncthreads();
#pragma unroll
    for (int r = 0; r < 8; r++) {
        int t = (tid << 3) | r;
        sm->amp[t + (t >> 3)] = make_ulonglong2(rev[r], imv[r]);
    }
    __syncthreads();
#pragma unroll
    for (int r = 0; r < 8; r++) {
        int t = ((tid >> 3) << 6) | (r << 3) | (tid & 7);
        ulonglong2 v = sm->amp[t + (t >> 3)];
        rev[r] = v.x; imv[r] = v.y;
    }

    // gates m3: bits 3,4,5
    level(rev, imv, sm->um[3], 1);
    level(rev, imv, sm->um[4], 2);
    level(rev, imv, sm->um[5], 4);

    // transpose m3 -> m4
    __syncthreads();
#pragma unroll
    for (int r = 0; r < 8; r++) {
        int t = ((tid >> 3) << 6) | (r << 3) | (tid & 7);
        sm->amp[t + (t >> 3)] = make_ulonglong2(rev[r], imv[r]);
    }
    __syncthreads();
#pragma unroll
    for (int r = 0; r < 8; r++) {
        int t = ((tid >> 5) << 8) | (r << 5) | (tid & 31);
        ulonglong2 v = sm->amp[t + (t >> 3)];
        rev[r] = v.x; imv[r] = v.y;
    }

    // gates m4: bits 6,7 (reg bits 1,2; reg bit 0 = t[5] already gated in m3)
    level(rev, imv, sm->um[6], 2);
    level(rev, imv, sm->um[7], 4);

    // store from m4
#pragma unroll
    for (int r = 0; r < 8; r++) {
        int t = ((tid >> 5) << 8) | (r << 5) | (tid & 31);
        dst[base + (tbase | t)] = make_ulonglong2(rev[r], imv[r]);
    }
}

// ---------------------------------------------------------------------------
// Pass B: tile = bits {15..11} + [5:0]; block id m = g[10:6] (5 bits).
// t(11b): t[10:6] = g[15:11], t[5:0] = g[5:0];  g = (t>>6)<<11 | m<<6 | (t&63)
// m1: t=(r<<8)|tid: reg bits t[10:8] = g[15:13] -> gates qubits 0,1,2
//     (um[k] = gate(qubit 2-k))
// m2: t=((tid>>5)<<8)|(r<<5)|(tid&31): t[7]=g12 (q3), t[6]=g11 (q4)
//     gates: s=2 -> um[3]=q4, s=4 -> um[4]=q3
// CNOT q=0..3 relabel: 5-bit suffix-XOR on h = t[10:6] in store address.
// ---------------------------------------------------------------------------
__global__ void __launch_bounds__(THREADS, 4)
passB(const ulonglong2* __restrict__ src, ulonglong2* __restrict__ dst,
      const float* __restrict__ vp, int layer) {
    __shared__ G7 um[5];
    __shared__ ulonglong2 ampsm[PAD_SLOTS];
    int tid = threadIdx.x;
    int pair = blockIdx.x >> 5, m = blockIdx.x & 31;
    int base = pair << 16;

    if (tid < 5) {
        int q = (tid < 3) ? (2 - tid) : (7 - tid);   // {2,1,0,4,3}
        make_u(vp, layer, q, &um[tid]);
    }
    __syncthreads();

    ull rev[8], imv[8];
#pragma unroll
    for (int r = 0; r < 8; r++) {
        int t = (r << 8) | tid;
        int g = ((t >> 6) << 11) | (m << 6) | (t & 63);
        ulonglong2 v = src[base + g];
        rev[r] = v.x; imv[r] = v.y;
    }

    // gates qubits 2,1,0 on reg bits 0,1,2
    level(rev, imv, um[0], 1);
    level(rev, imv, um[1], 2);
    level(rev, imv, um[2], 4);

    // transpose m1 -> m2
#pragma unroll
    for (int r = 0; r < 8; r++) {
        int t = (r << 8) | tid;
        ampsm[t + (t >> 3)] = make_ulonglong2(rev[r], imv[r]);
    }
    __syncthreads();
#pragma unroll
    for (int r = 0; r < 8; r++) {
        int t = ((tid >> 5) << 8) | (r << 5) | (tid & 31);
        ulonglong2 v = ampsm[t + (t >> 3)];
        rev[r] = v.x; imv[r] = v.y;
    }

    // gates qubit 4 (t[6], s=2) and qubit 3 (t[7], s=4)
    level(rev, imv, um[3], 2);
    level(rev, imv, um[4], 4);

    // store with CNOT q=0..3 relabel: suffix-XOR on h = g[15:11]
#pragma unroll
    for (int r = 0; r < 8; r++) {
        int t = ((tid >> 5) << 8) | (r << 5) | (tid & 31);
        int h = t >> 6;                       // 5 bits
        h ^= h >> 1; h ^= h >> 2; h ^= h >> 4;
        int gp = (h << 11) | (m << 6) | (t & 63);
        dst[base + gp] = make_ulonglong2(rev[r], imv[r]);
    }
}

// ---------------------------------------------------------------------------
// Pass B measure: gates qubits 0..4, fold ENTIRE final CNOT chain into the
// parity (final bit k = parity(j >> k)), reduce Z expectations per batch
// lane, apply linear head.
// ---------------------------------------------------------------------------
__global__ void __launch_bounds__(THREADS, 2)
passBmeas(const ulonglong2* __restrict__ src, const float* __restrict__ vp,
          const float* __restrict__ hw, float* __restrict__ out, int layer) {
    __shared__ G7 um[5];
    __shared__ ulonglong2 ampsm[PAD_SLOTS];
    __shared__ float feats[2][16];
    int tid = threadIdx.x;
    int l = tid & 31;
    int pair = blockIdx.x >> 5, m = blockIdx.x & 31;
    int base = pair << 16;

    if (tid < 5) {
        int q = (tid < 3) ? (2 - tid) : (7 - tid);
        make_u(vp, layer, q, &um[tid]);
    }
    if (tid < 32) feats[tid >> 4][tid & 15] = 0.0f;
    __syncthreads();

    ull rev[8], imv[8];
#pragma unroll
    for (int r = 0; r < 8; r++) {
        int t = (r << 8) | tid;
        int g = ((t >> 6) << 11) | (m << 6) | (t & 63);
        ulonglong2 v = src[base + g];
        rev[r] = v.x; imv[r] = v.y;
    }

    level(rev, imv, um[0], 1);
    level(rev, imv, um[1], 2);
    level(rev, imv, um[2], 4);

#pragma unroll
    for (int r = 0; r < 8; r++) {
        int t = (r << 8) | tid;
        ampsm[t + (t >> 3)] = make_ulonglong2(rev[r], imv[r]);
    }
    __syncthreads();
#pragma unroll
    for (int r = 0; r < 8; r++) {
        int t = ((tid >> 5) << 8) | (r << 5) | (tid & 31);
        ulonglong2 v = ampsm[t + (t >> 3)];
        rev[r] = v.x; imv[r] = v.y;
    }

    level(rev, imv, um[3], 2);
    level(rev, imv, um[4], 4);

    ull acc[16];
#pragma unroll
    for (int q = 0; q < 16; q++) acc[q] = pk(0.0f, 0.0f);
#pragma unroll
    for (int r = 0; r < 8; r++) {
        int t = ((tid >> 5) << 8) | (r << 5) | (tid & 31);
        int j = ((t >> 6) << 11) | (m << 6) | (t & 63);
        ull p = f2fma(rev[r], rev[r], f2mul(imv[r], imv[r]));  // per-batch prob
        int f = j;                            // suffix-XOR parity
        f ^= f >> 1; f ^= f >> 2; f ^= f >> 4; f ^= f >> 8;
#pragma unroll
        for (int q = 0; q < 16; q++)
            acc[q] = ((f >> (15 - q)) & 1) ? f2sub(acc[q], p) : f2add(acc[q], p);
    }
#pragma unroll
    for (int q = 0; q < 16; q++) {
#pragma unroll
        for (int off = 16; off; off >>= 1)
            acc[q] = f2add(acc[q], __shfl_xor_sync(0xffffffffu, acc[q], off));
    }
    if (l == 0) {
#pragma unroll
        for (int q = 0; q < 16; q++) {
            float a0, a1; upk(acc[q], a0, a1);
            atomicAdd(&feats[0][q], a0);
            atomicAdd(&feats[1][q], a1);
        }
    }
    __syncthreads();
    if (tid == 0) {
        float v0 = 0.0f, v1 = 0.0f;
        for (int q = 0; q < 16; q++) {
            v0 += feats[0][q] * hw[q];
            v1 += feats[1][q] * hw[q];
        }
        atomicAdd(&out[pair * 2], v0);
        atomicAdd(&out[pair * 2 + 1], v1);
    }
}

__global__ void initOut(float* __restrict__ out, const float* __restrict__ hb) {
    if (threadIdx.x < 64) out[threadIdx.x] = hb[0];
}

extern "C" void kernel_launch(void* const* d_in, const int* in_sizes, int n_in,
                              void* d_out, int out_size) {
    const float* sr = (const float*)d_in[0];
    const float* si = (const float*)d_in[1];
    const float* vp = (const float*)d_in[2];
    const float* hw = (const float*)d_in[3];
    const float* hb = (const float*)d_in[4];
    float* out = (float*)d_out;

    cudaFuncSetAttribute(passA, cudaFuncAttributeMaxDynamicSharedMemorySize, SMEM_BYTES);

    ulonglong2 *b0, *b1;
    cudaGetSymbolAddress((void**)&b0, g_bufA);
    cudaGetSymbolAddress((void**)&b1, g_bufB);

    initOut<<<1, 64>>>(out, hb);
    // layer 0
    passA<<<1024, THREADS, SMEM_BYTES>>>(sr, si, nullptr, b0, vp, 0, 0, 1);
    passB<<<1024, THREADS>>>(b0, b1, vp, 0);
    // layer 1 (load applies layer-0 CNOT chain q=4..14)
    passA<<<1024, THREADS, SMEM_BYTES>>>(nullptr, nullptr, b1, b0, vp, 1, 1, 0);
    passB<<<1024, THREADS>>>(b0, b1, vp, 1);
    // layer 2
    passA<<<1024, THREADS, SMEM_BYTES>>>(nullptr, nullptr, b1, b0, vp, 2, 1, 0);
    passBmeas<<<1024, THREADS>>>(b0, vp, hw, out, 2);
}

// round 10
// speedup vs baseline: 1.0436x; 1.0339x over previous
#include <cuda_runtime.h>
#include <cstdint>

// ============================================================================
// 16-qubit statevector simulator, 64 batches, 3 layers (Rot x16 + CNOT chain).
// Round 10: R9 slot-pair SoA with the in-lane coefficient fix (p3/p4 lane-1
// signs). f32x2 packs TWO AMPLITUDE SLOTS (same batch): rev[8]/imv[8] hold
// 16 amps in 32 regs. Per 4-bit gate group: 3 swap-free vgate levels + 1
// in-lane level. Swaps/thread: 384 -> 48. passB/passBmeas = R6 versions.
// ============================================================================

#define THREADS   256
#define TILE      4096
#define PAD_SLOTS (TILE + (TILE >> 4))   // 4352, slot = t + (t>>4), 8B words

typedef unsigned long long ull;

__device__ ull g_bufA[64 * 65536];
__device__ ull g_bufB[64 * 65536];

struct G7 { ull ar, ai, nai, br, bi, nbr, nbi; };        // vgate coeffs
struct GL { ull p1, p2, p3, p4, q1, q2, q3, q4; };       // in-lane coeffs

struct Smem {
    ull amp[PAD_SLOTS];
    G7  umv[12];
    GL  uml[3];
};
#define SMEM_BYTES ((int)sizeof(Smem))

struct SmemB {
    ull   um[4][8];
    float feats[16];
};

// ---------------- packed f32x2 primitives ----------------
__device__ __forceinline__ ull f2fma(ull a, ull b, ull c) {
    ull d; asm("fma.rn.f32x2 %0, %1, %2, %3;" : "=l"(d) : "l"(a), "l"(b), "l"(c));
    return d;
}
__device__ __forceinline__ ull f2mul(ull a, ull b) {
    ull d; asm("mul.rn.f32x2 %0, %1, %2;" : "=l"(d) : "l"(a), "l"(b));
    return d;
}
__device__ __forceinline__ ull pk(float lo, float hi) {
    ull r; asm("mov.b64 %0, {%1, %2};" : "=l"(r) : "f"(lo), "f"(hi));
    return r;
}
__device__ __forceinline__ void upk(ull v, float& lo, float& hi) {
    asm("mov.b64 {%0, %1}, %2;" : "=f"(lo), "=f"(hi) : "l"(v));
}
__device__ __forceinline__ ull swp(ull v) {
    float lo, hi; upk(v, lo, hi); return pk(hi, lo);
}

// split slot-pair (re2,im2) into two packed amps (re,im)
__device__ __forceinline__ void lane_amps(ull re2, ull im2, ull& a0, ull& a1) {
    float rl, rh, il, ih;
    upk(re2, rl, rh); upk(im2, il, ih);
    a0 = pk(rl, il); a1 = pk(rh, ih);
}
// combine two packed amps into a slot-pair (re2,im2)
__device__ __forceinline__ void pair_amps(ull a0, ull a1, ull& re2, ull& im2) {
    float r0, i0, r1, i1;
    upk(a0, r0, i0); upk(a1, r1, i1);
    re2 = pk(r0, r1); im2 = pk(i0, i1);
}

// row0 of U = Rz@Ry@Rx (SU(2)): u00 = (u0,u1), u01 = (u2,u3)
__device__ __forceinline__ void make_row(const float* __restrict__ vp, int layer, int q,
                                         float& u0, float& u1, float& u2, float& u3) {
    const float* p = vp + ((layer * 16) + q) * 6;
    float tx = p[0], ty = p[1], tz = p[2];
    float cx = cosf(0.5f * tx), sx = sinf(0.5f * tx);
    float cy = cosf(0.5f * ty), sy = sinf(0.5f * ty);
    float cz = cosf(0.5f * tz), sz = sinf(0.5f * tz);
    float m00r =  cy * cx, m00i =  sy * sx;
    float m01r = -sy * cx, m01i = -cy * sx;
    u0 = cz * m00r + sz * m00i; u1 = cz * m00i - sz * m00r;
    u2 = cz * m01r + sz * m01i; u3 = cz * m01i - sz * m01r;
}
__device__ __forceinline__ void make_g7(const float* vp, int layer, int q, G7* g) {
    float u0, u1, u2, u3; make_row(vp, layer, q, u0, u1, u2, u3);
    g->ar  = pk(u0, u0);  g->ai  = pk(u1, u1);  g->nai = pk(-u1, -u1);
    g->br  = pk(u2, u2);  g->bi  = pk(u3, u3);
    g->nbr = pk(-u2, -u2); g->nbi = pk(-u3, -u3);
}
// in-lane coefficients (lane0 = side0, lane1 = side1 of the gate pair):
// nr0 = u0*r0 + u2*r1 - u1*i0 - u3*i1
// nr1 = u0*r1 - u2*r0 + u1*i1 - u3*i0
// ni0 = u1*r0 + u3*r1 + u0*i0 + u2*i1
// ni1 = -u1*r1 + u3*r0 + u0*i1 - u2*i0
__device__ __forceinline__ void make_gl(const float* vp, int layer, int q, GL* g) {
    float u0, u1, u2, u3; make_row(vp, layer, q, u0, u1, u2, u3);
    g->p1 = pk(u0, u0);   g->p2 = pk(u2, -u2);
    g->p3 = pk(-u1, u1);  g->p4 = pk(-u3, -u3);   // <- fixed lane-1 signs
    g->q1 = pk(u1, -u1);  g->q2 = pk(u3, u3);
    g->q3 = pk(u0, u0);   g->q4 = pk(u2, -u2);
}
// packed-complex coeffs for passB (R6 form)
__device__ __forceinline__ void make_u8(const float* vp, int layer, int q, ull* u8) {
    float u0, u1, u2, u3; make_row(vp, layer, q, u0, u1, u2, u3);
    float u4 = -u2, u5 = u3, u6 = u0, u7 = -u1;   // row1 = (-u01*, u00*)
    u8[0] = pk(u0, u0); u8[1] = pk(-u1, u1);
    u8[2] = pk(u2, u2); u8[3] = pk(-u3, u3);
    u8[4] = pk(u4, u4); u8[5] = pk(-u5, u5);
    u8[6] = pk(u6, u6); u8[7] = pk(-u7, u7);
}

// swap-free SoA gate between slot-pairs a and b (4 amps = 2 pairs)
__device__ __forceinline__ void vgate(ull& rea, ull& ima, ull& reb, ull& imb,
                                      const G7& g) {
    ull nra = f2fma(g.ar,  rea, f2fma(g.nai, ima, f2fma(g.br,  reb, f2mul(g.nbi, imb))));
    ull nia = f2fma(g.ai,  rea, f2fma(g.ar,  ima, f2fma(g.bi,  reb, f2mul(g.br,  imb))));
    ull nrb = f2fma(g.nbr, rea, f2fma(g.nbi, ima, f2fma(g.ar,  reb, f2mul(g.ai,  imb))));
    ull nib = f2fma(g.bi,  rea, f2fma(g.nbr, ima, f2fma(g.nai, reb, f2mul(g.ar,  imb))));
    rea = nra; ima = nia; reb = nrb; imb = nib;
}

__device__ __forceinline__ void level3(ull* __restrict__ rev, ull* __restrict__ imv,
                                       const G7& gsm, int s) {
    G7 g = gsm;
#pragma unroll
    for (int r0 = 0; r0 < 8; r0++) {
        if (r0 & s) continue;
        vgate(rev[r0], imv[r0], rev[r0 | s], imv[r0 | s], g);
    }
}

// in-lane gate: the two amps inside one f32x2 are the gate pair
__device__ __forceinline__ void inlane(ull* __restrict__ rev, ull* __restrict__ imv,
                                       const GL& gsm) {
    GL g = gsm;
#pragma unroll
    for (int k = 0; k < 8; k++) {
        ull sR = swp(rev[k]), sI = swp(imv[k]);
        ull nR = f2fma(g.p1, rev[k], f2fma(g.p2, sR, f2fma(g.p3, imv[k], f2mul(g.p4, sI))));
        ull nI = f2fma(g.q1, rev[k], f2fma(g.q2, sR, f2fma(g.q3, imv[k], f2mul(g.q4, sI))));
        rev[k] = nR; imv[k] = nI;
    }
}

// packed-complex pair gate for passB (R6)
__device__ __forceinline__ void cgate2(ull& a, ull& b, const ull* __restrict__ u) {
    ull u0 = u[0], u1 = u[1], u2 = u[2], u3 = u[3];
    ull u4 = u[4], u5 = u[5], u6 = u[6], u7 = u[7];
    ull na = f2fma(u0, a, f2fma(u1, swp(a), f2fma(u2, b, f2mul(u3, swp(b)))));
    ull nb = f2fma(u4, a, f2fma(u5, swp(a), f2fma(u6, b, f2mul(u7, swp(b)))));
    a = na; b = nb;
}
__device__ __forceinline__ void gate4(ull* __restrict__ amp,
                                      const ull (* __restrict__ um)[8], int b0) {
#pragma unroll
    for (int k = 0; k < 4; k++) {
        int s = 1 << k;
#pragma unroll
        for (int r0 = 0; r0 < 16; r0++) {
            if (r0 & s) continue;
            cgate2(amp[r0], amp[r0 | s], um[b0 + k]);
        }
    }
}

// ---------------------------------------------------------------------------
// Pass A: tile = bits [11:0], tile id = bits [15:12]; grid = batch(6b)<<4|tile.
// permLoad applies prev-layer CNOTs q=4..14: a = i ^ ((i>>1) & 0x7FF).
// m1: t = (k<<9)|(p<<8)|tid  -> vgates bits 9,10,11; in-lane bit 8
// m2: t = (tid<<4)|(k<<1)|p  -> vgates bits 1,2,3;   in-lane bit 0
// m3: t = ((tid>>4)<<8)|(k<<5)|(p<<4)|(tid&15) -> vgates 5,6,7; in-lane 4
// umv[b] = vgate coeffs for tile bit b (qubit 15-b); uml[0/1/2] = bits 0/4/8.
// ---------------------------------------------------------------------------
__global__ void __launch_bounds__(THREADS, 4)
passA(const float* __restrict__ sr, const float* __restrict__ si,
      const ull* __restrict__ src, ull* __restrict__ dst,
      const float* __restrict__ vp, int layer, int permLoad, int fromInput) {
    extern __shared__ char smraw[];
    Smem* sm = (Smem*)smraw;
    int tid = threadIdx.x;
    int batch = blockIdx.x >> 4, tile = blockIdx.x & 15;
    int base  = batch << 16;
    int tbase = tile << 12;

    if (tid < 12) make_g7(vp, layer, 15 - tid, &sm->umv[tid]);
    else if (tid < 15) {
        int b = (tid - 12) * 4;                  // bits 0,4,8
        make_gl(vp, layer, 15 - b, &sm->uml[tid - 12]);
    }
    __syncthreads();

    ull rev[8], imv[8];

    // ---- load in m1 (pair over t8) ----
    if (fromInput) {
#pragma unroll
        for (int k = 0; k < 8; k++) {
            int j0 = tbase | (k << 9) | tid;
            int j1 = j0 | 0x100;
            rev[k] = pk(sr[base + j0], sr[base + j1]);
            imv[k] = pk(si[base + j0], si[base + j1]);
        }
    } else if (permLoad) {
#pragma unroll
        for (int k = 0; k < 8; k++) {
            int j0 = tbase | (k << 9) | tid;
            int j1 = j0 | 0x100;
            int a0 = j0 ^ ((j0 >> 1) & 0x7FF);
            int a1 = j1 ^ ((j1 >> 1) & 0x7FF);
            ull A = src[base + a0], B = src[base + a1];
            pair_amps(A, B, rev[k], imv[k]);
        }
    } else {
#pragma unroll
        for (int k = 0; k < 8; k++) {
            int j0 = tbase | (k << 9) | tid;
            ull A = src[base + j0], B = src[base + (j0 | 0x100)];
            pair_amps(A, B, rev[k], imv[k]);
        }
    }

    // ---- group m1: vgates bits 9,10,11 + in-lane bit 8 ----
    level3(rev, imv, sm->umv[9], 1);
    level3(rev, imv, sm->umv[10], 2);
    level3(rev, imv, sm->umv[11], 4);
    inlane(rev, imv, sm->uml[2]);

    // ---- transpose m1 -> m2 ----
#pragma unroll
    for (int k = 0; k < 8; k++) {
        ull a0, a1; lane_amps(rev[k], imv[k], a0, a1);
        int t0 = (k << 9) | tid;            // p=0
        int t1 = t0 | 0x100;                // p=1
        sm->amp[t0 + (t0 >> 4)] = a0;
        sm->amp[t1 + (t1 >> 4)] = a1;
    }
    __syncthreads();
#pragma unroll
    for (int k = 0; k < 8; k++) {
        int t0 = (tid << 4) | (k << 1);     // p=0
        int t1 = t0 | 1;                    // p=1
        ull a0 = sm->amp[t0 + (t0 >> 4)];
        ull a1 = sm->amp[t1 + (t1 >> 4)];
        pair_amps(a0, a1, rev[k], imv[k]);
    }

    // ---- group m2: vgates bits 1,2,3 + in-lane bit 0 ----
    level3(rev, imv, sm->umv[1], 1);
    level3(rev, imv, sm->umv[2], 2);
    level3(rev, imv, sm->umv[3], 4);
    inlane(rev, imv, sm->uml[0]);

    // ---- transpose m2 -> m3 ----
    __syncthreads();
#pragma unroll
    for (int k = 0; k < 8; k++) {
        ull a0, a1; lane_amps(rev[k], imv[k], a0, a1);
        int t0 = (tid << 4) | (k << 1);
        int t1 = t0 | 1;
        sm->amp[t0 + (t0 >> 4)] = a0;
        sm->amp[t1 + (t1 >> 4)] = a1;
    }
    __syncthreads();
#pragma unroll
    for (int k = 0; k < 8; k++) {
        int t0 = ((tid >> 4) << 8) | (k << 5) | (tid & 15);   // p=0
        int t1 = t0 | 0x10;                                    // p=1
        ull a0 = sm->amp[t0 + (t0 >> 4)];
        ull a1 = sm->amp[t1 + (t1 >> 4)];
        pair_amps(a0, a1, rev[k], imv[k]);
    }

    // ---- group m3: vgates bits 5,6,7 + in-lane bit 4 ----
    level3(rev, imv, sm->umv[5], 1);
    level3(rev, imv, sm->umv[6], 2);
    level3(rev, imv, sm->umv[7], 4);
    inlane(rev, imv, sm->uml[1]);

    // ---- store from m3 ----
#pragma unroll
    for (int k = 0; k < 8; k++) {
        ull a0, a1; lane_amps(rev[k], imv[k], a0, a1);
        int t0 = ((tid >> 4) << 8) | (k << 5) | (tid & 15);
        dst[base + (tbase | t0)] = a0;
        dst[base + (tbase | t0 | 0x10)] = a1;
    }
}

// ---------------------------------------------------------------------------
// Pass B (R6): t=(r<<8)|tid, g = (t[11:7]<<11)|(m<<7)|t[6:0]. Reg bits =
// g[15:12] = qubits 3..0. CNOT q=0..3 relabel = suffix-XOR on g[15:11] folded
// into the store address. Pure register kernel.
// ---------------------------------------------------------------------------
__global__ void __launch_bounds__(THREADS, 4)
passB(const ull* __restrict__ src, ull* __restrict__ dst,
      const float* __restrict__ vp, int layer) {
    __shared__ SmemB sm;
    int tid = threadIdx.x;
    int batch = blockIdx.x >> 4, m = blockIdx.x & 15;
    int base = batch << 16;

    if (tid < 4) make_u8(vp, layer, 3 - tid, sm.um[tid]);  // um[k]: qubit 3-k
    __syncthreads();

    ull amp[16];
#pragma unroll
    for (int r = 0; r < 16; r++) {
        int t = (r << 8) | tid;
        int g = ((t >> 7) << 11) | (m << 7) | (t & 0x7F);
        amp[r] = src[base + g];
    }

    gate4(amp, sm.um, 0);

#pragma unroll
    for (int r = 0; r < 16; r++) {
        int t = (r << 8) | tid;
        int h = t >> 7;                     // 5 bits = g[15:11]
        h ^= h >> 1; h ^= h >> 2; h ^= h >> 4;
        int gp = (h << 11) | (m << 7) | (t & 0x7F);
        dst[base + gp] = amp[r];
    }
}

// ---------------------------------------------------------------------------
// Pass B measure (R6): gates qubits 0..3, fold entire final CNOT chain into
// the parity, reduce Z expectations, apply linear head.
// ---------------------------------------------------------------------------
__global__ void __launch_bounds__(THREADS, 4)
passBmeas(const ull* __restrict__ src, const float* __restrict__ vp,
          const float* __restrict__ hw, float* __restrict__ out, int layer) {
    __shared__ SmemB sm;
    int tid = threadIdx.x;
    int l = tid & 31;
    int batch = blockIdx.x >> 4, m = blockIdx.x & 15;
    int base = batch << 16;

    if (tid < 4) make_u8(vp, layer, 3 - tid, sm.um[tid]);
    if (tid < 16) sm.feats[tid] = 0.0f;
    __syncthreads();

    ull amp[16];
#pragma unroll
    for (int r = 0; r < 16; r++) {
        int t = (r << 8) | tid;
        int g = ((t >> 7) << 11) | (m << 7) | (t & 0x7F);
        amp[r] = src[base + g];
    }

    gate4(amp, sm.um, 0);

    float acc[16];
#pragma unroll
    for (int q = 0; q < 16; q++) acc[q] = 0.0f;
#pragma unroll
    for (int r = 0; r < 16; r++) {
        int t = (r << 8) | tid;
        int j = ((t >> 7) << 11) | (m << 7) | (t & 0x7F);
        float re, im; upk(amp[r], re, im);
        float p = re * re + im * im;
        int f = j;                           // suffix-XOR parity
        f ^= f >> 1; f ^= f >> 2; f ^= f >> 4; f ^= f >> 8;
#pragma unroll
        for (int q = 0; q < 16; q++)
            acc[q] += ((f >> (15 - q)) & 1) ? -p : p;
    }
#pragma unroll
    for (int q = 0; q < 16; q++) {
#pragma unroll
        for (int off = 16; off; off >>= 1)
            acc[q] += __shfl_xor_sync(0xffffffffu, acc[q], off);
    }
    if (l == 0) {
#pragma unroll
        for (int q = 0; q < 16; q++) atomicAdd(&sm.feats[q], acc[q]);
    }
    __syncthreads();
    if (tid == 0) {
        float v = 0.0f;
        for (int q = 0; q < 16; q++) v += sm.feats[q] * hw[q];
        atomicAdd(&out[batch], v);
    }
}

__global__ void initOut(float* __restrict__ out, const float* __restrict__ hb) {
    if (threadIdx.x < 64) out[threadIdx.x] = hb[0];
}

extern "C" void kernel_launch(void* const* d_in, const int* in_sizes, int n_in,
                              void* d_out, int out_size) {
    const float* sr = (const float*)d_in[0];
    const float* si = (const float*)d_in[1];
    const float* vp = (const float*)d_in[2];
    const float* hw = (const float*)d_in[3];
    const float* hb = (const float*)d_in[4];
    float* out = (float*)d_out;

    cudaFuncSetAttribute(passA, cudaFuncAttributeMaxDynamicSharedMemorySize, SMEM_BYTES);

    ull *b0, *b1;
    cudaGetSymbolAddress((void**)&b0, g_bufA);
    cudaGetSymbolAddress((void**)&b1, g_bufB);

    initOut<<<1, 64>>>(out, hb);
    // layer 0
    passA<<<1024, THREADS, SMEM_BYTES>>>(sr, si, nullptr, b0, vp, 0, 0, 1);
    passB<<<1024, THREADS>>>(b0, b1, vp, 0);
    // layer 1 (load applies layer-0 CNOT chain q=4..14)
    passA<<<1024, THREADS, SMEM_BYTES>>>(nullptr, nullptr, b1, b0, vp, 1, 1, 0);
    passB<<<1024, THREADS>>>(b0, b1, vp, 1);
    // layer 2
    passA<<<1024, THREADS, SMEM_BYTES>>>(nullptr, nullptr, b1, b0, vp, 2, 1, 0);
    passBmeas<<<1024, THREADS>>>(b0, vp, hw, out, 2);
}

// round 11
// speedup vs baseline: 1.0469x; 1.0032x over previous
#include <cuda_runtime.h>
#include <cstdint>

// ============================================================================
// 16-qubit statevector simulator, 64 batches, 3 layers (Rot x16 + CNOT chain).
// Round 11: pack f32x2 over BIT 15 (qubit 0) — a bit passA never touches.
//  * Global state: ulonglong2[batch][2^15]; elem j = {(re(j),re(j|0x8000)),
//    (im(j),im(j|0x8000))}. passA (qubits 5..15, j bits [10:0]) sees pure
//    SoA: every gate is a swap-free vgate; 16B gmem/smem ops; no repacking.
//  * passB: qubits 1..4 as vgates (3 reg levels + 1 transpose), qubit 0 as
//    in-lane gate (R10-verified GL coeffs). NO CNOT relabels here.
//  * ENTIRE CNOT chain q=0..14 deferred to next passA's load perm
//    a = i ^ (i>>1): bit15 invariant; lane1 row = a0 ^ 0x4000.
//    Final layer's chain folds into measurement parity (lane1 flips all
//    signs -> one packed (1,-1) multiply).
// ============================================================================

#define THREADS   256
#define PAD_SLOTS (2048 + 256)    // slot = t + (t>>3), 16B elements

typedef unsigned long long ull;

__device__ ulonglong2 g_bufA[64 * 32768];
__device__ ulonglong2 g_bufB[64 * 32768];

struct G7 { ull ar, ai, nai, br, bi, nbr, nbi; };   // swap-free vgate coeffs
struct GL { ull p1, p2, p3, p4, q1, q2, q3, q4; };  // in-lane (bit15) coeffs

// ---------------- packed f32x2 primitives ----------------
__device__ __forceinline__ ull f2fma(ull a, ull b, ull c) {
    ull d; asm("fma.rn.f32x2 %0, %1, %2, %3;" : "=l"(d) : "l"(a), "l"(b), "l"(c));
    return d;
}
__device__ __forceinline__ ull f2mul(ull a, ull b) {
    ull d; asm("mul.rn.f32x2 %0, %1, %2;" : "=l"(d) : "l"(a), "l"(b));
    return d;
}
__device__ __forceinline__ ull f2add(ull a, ull b) {
    ull d; asm("add.rn.f32x2 %0, %1, %2;" : "=l"(d) : "l"(a), "l"(b));
    return d;
}
__device__ __forceinline__ ull f2sub(ull a, ull b) {
    ull d; asm("sub.rn.f32x2 %0, %1, %2;" : "=l"(d) : "l"(a), "l"(b));
    return d;
}
__device__ __forceinline__ ull pk(float lo, float hi) {
    ull r; asm("mov.b64 %0, {%1, %2};" : "=l"(r) : "f"(lo), "f"(hi));
    return r;
}
__device__ __forceinline__ void upk(ull v, float& lo, float& hi) {
    asm("mov.b64 {%0, %1}, %2;" : "=f"(lo), "=f"(hi) : "l"(v));
}
__device__ __forceinline__ ull swp(ull v) {
    float lo, hi; upk(v, lo, hi); return pk(hi, lo);
}

// row0 of U = Rz@Ry@Rx (SU(2)): u00 = (u0,u1), u01 = (u2,u3)
__device__ __forceinline__ void make_row(const float* __restrict__ vp, int layer, int q,
                                         float& u0, float& u1, float& u2, float& u3) {
    const float* p = vp + ((layer * 16) + q) * 6;
    float tx = p[0], ty = p[1], tz = p[2];
    float cx = cosf(0.5f * tx), sx = sinf(0.5f * tx);
    float cy = cosf(0.5f * ty), sy = sinf(0.5f * ty);
    float cz = cosf(0.5f * tz), sz = sinf(0.5f * tz);
    float m00r =  cy * cx, m00i =  sy * sx;
    float m01r = -sy * cx, m01i = -cy * sx;
    u0 = cz * m00r + sz * m00i; u1 = cz * m00i - sz * m00r;
    u2 = cz * m01r + sz * m01i; u3 = cz * m01i - sz * m01r;
}
__device__ __forceinline__ void make_g7(const float* vp, int layer, int q, G7* g) {
    float u0, u1, u2, u3; make_row(vp, layer, q, u0, u1, u2, u3);
    g->ar  = pk(u0, u0);  g->ai  = pk(u1, u1);  g->nai = pk(-u1, -u1);
    g->br  = pk(u2, u2);  g->bi  = pk(u3, u3);
    g->nbr = pk(-u2, -u2); g->nbi = pk(-u3, -u3);
}
// in-lane coeffs (lane0 = bit15 clear, lane1 = set) — R10-verified
__device__ __forceinline__ void make_gl(const float* vp, int layer, int q, GL* g) {
    float u0, u1, u2, u3; make_row(vp, layer, q, u0, u1, u2, u3);
    g->p1 = pk(u0, u0);   g->p2 = pk(u2, -u2);
    g->p3 = pk(-u1, u1);  g->p4 = pk(-u3, -u3);
    g->q1 = pk(u1, -u1);  g->q2 = pk(u3, u3);
    g->q3 = pk(u0, u0);   g->q4 = pk(u2, -u2);
}

// swap-free SoA SU(2) gate on slot pair (a,b), both lanes simultaneously
__device__ __forceinline__ void vgate(ull& rea, ull& ima, ull& reb, ull& imb,
                                      const G7& g) {
    ull nra = f2fma(g.ar,  rea, f2fma(g.nai, ima, f2fma(g.br,  reb, f2mul(g.nbi, imb))));
    ull nia = f2fma(g.ai,  rea, f2fma(g.ar,  ima, f2fma(g.bi,  reb, f2mul(g.br,  imb))));
    ull nrb = f2fma(g.nbr, rea, f2fma(g.nbi, ima, f2fma(g.ar,  reb, f2mul(g.ai,  imb))));
    ull nib = f2fma(g.bi,  rea, f2fma(g.nbr, ima, f2fma(g.nai, reb, f2mul(g.ar,  imb))));
    rea = nra; ima = nia; reb = nrb; imb = nib;
}

__device__ __forceinline__ void level(ull* __restrict__ rev, ull* __restrict__ imv,
                                      const G7& gsm, int s) {
    G7 g = gsm;
#pragma unroll
    for (int r0 = 0; r0 < 8; r0++) {
        if (r0 & s) continue;
        vgate(rev[r0], imv[r0], rev[r0 | s], imv[r0 | s], g);
    }
}

// in-lane gate across bit 15 (the packed lane)
__device__ __forceinline__ void inlane8(ull* __restrict__ rev, ull* __restrict__ imv,
                                        const GL& gsm) {
    GL g = gsm;
#pragma unroll
    for (int k = 0; k < 8; k++) {
        ull sR = swp(rev[k]), sI = swp(imv[k]);
        ull nR = f2fma(g.p1, rev[k], f2fma(g.p2, sR, f2fma(g.p3, imv[k], f2mul(g.p4, sI))));
        ull nI = f2fma(g.q1, rev[k], f2fma(g.q2, sR, f2fma(g.q3, imv[k], f2mul(g.q4, sI))));
        rev[k] = nR; imv[k] = nI;
    }
}

// ---------------------------------------------------------------------------
// Pass A: rotations qubits 5..15 (j bits [10:0]). Tile = j[10:0] (2048 rows),
// tile id = j[14:11]; grid = batch(6b)<<4 | tile(4b). If !fromInput, the load
// applies the previous layer's FULL CNOT chain q=0..14: row a0 = j ^ (j>>1),
// lane0 from lo-halves of [a0], lane1 from hi-halves of [a0 ^ 0x4000].
// m1: t=(k<<8)|tid (bits 10..8 = q5,6,7)   m2: t=(tid<<3)|k (bits 2..0 = q13,14,15)
// m3: t=((tid>>3)<<6)|(k<<3)|(tid&7) (bits 5..3 = q10,11,12)
// m4: t=((tid>>5)<<8)|(k<<5)|(tid&31) (bits 7,6 = q8,9)
// um[b] = gate(qubit 15-b), b = 0..10.
// ---------------------------------------------------------------------------
__global__ void __launch_bounds__(THREADS, 4)
passA(const float* __restrict__ sr, const float* __restrict__ si,
      const ulonglong2* __restrict__ src, ulonglong2* __restrict__ dst,
      const float* __restrict__ vp, int layer, int fromInput) {
    __shared__ ulonglong2 amp[PAD_SLOTS];
    __shared__ G7 um[11];
    int tid = threadIdx.x;
    int batch = blockIdx.x >> 4, tileid = blockIdx.x & 15;
    int base  = batch << 15;
    int tbase = tileid << 11;

    if (tid < 11) make_g7(vp, layer, 15 - tid, &um[tid]);
    __syncthreads();

    ull rev[8], imv[8];

    if (fromInput) {
        const float* srb = sr + (batch << 16);
        const float* sib = si + (batch << 16);
#pragma unroll
        for (int k = 0; k < 8; k++) {
            int j = tbase | (k << 8) | tid;
            rev[k] = pk(srb[j], srb[j | 0x8000]);
            imv[k] = pk(sib[j], sib[j | 0x8000]);
        }
    } else {
#pragma unroll
        for (int k = 0; k < 8; k++) {
            int j = tbase | (k << 8) | tid;
            int a0 = j ^ (j >> 1);                 // chain q=0..14, lane 0
            ulonglong2 v0 = src[base + a0];
            ulonglong2 v1 = src[base + (a0 ^ 0x4000)];  // lane 1 row
            float rl, rd0, rd1, rh, il, id0, id1, ih;
            upk(v0.x, rl, rd0); upk(v1.x, rd1, rh);
            upk(v0.y, il, id0); upk(v1.y, id1, ih);
            rev[k] = pk(rl, rh);
            imv[k] = pk(il, ih);
        }
    }

    // m1: bits 8,9,10 (qubits 7,6,5)
    level(rev, imv, um[8], 1);
    level(rev, imv, um[9], 2);
    level(rev, imv, um[10], 4);

    // transpose m1 -> m2
#pragma unroll
    for (int k = 0; k < 8; k++) {
        int t = (k << 8) | tid;
        amp[t + (t >> 3)] = make_ulonglong2(rev[k], imv[k]);
    }
    __syncthreads();
#pragma unroll
    for (int k = 0; k < 8; k++) {
        int t = (tid << 3) | k;
        ulonglong2 v = amp[t + (t >> 3)];
        rev[k] = v.x; imv[k] = v.y;
    }

    // m2: bits 0,1,2 (qubits 15,14,13)
    level(rev, imv, um[0], 1);
    level(rev, imv, um[1], 2);
    level(rev, imv, um[2], 4);

    // transpose m2 -> m3
    __syncthreads();
#pragma unroll
    for (int k = 0; k < 8; k++) {
        int t = (tid << 3) | k;
        amp[t + (t >> 3)] = make_ulonglong2(rev[k], imv[k]);
    }
    __syncthreads();
#pragma unroll
    for (int k = 0; k < 8; k++) {
        int t = ((tid >> 3) << 6) | (k << 3) | (tid & 7);
        ulonglong2 v = amp[t + (t >> 3)];
        rev[k] = v.x; imv[k] = v.y;
    }

    // m3: bits 3,4,5 (qubits 12,11,10)
    level(rev, imv, um[3], 1);
    level(rev, imv, um[4], 2);
    level(rev, imv, um[5], 4);

    // transpose m3 -> m4
    __syncthreads();
#pragma unroll
    for (int k = 0; k < 8; k++) {
        int t = ((tid >> 3) << 6) | (k << 3) | (tid & 7);
        amp[t + (t >> 3)] = make_ulonglong2(rev[k], imv[k]);
    }
    __syncthreads();
#pragma unroll
    for (int k = 0; k < 8; k++) {
        int t = ((tid >> 5) << 8) | (k << 5) | (tid & 31);
        ulonglong2 v = amp[t + (t >> 3)];
        rev[k] = v.x; imv[k] = v.y;
    }

    // m4: bits 6,7 (qubits 9,8); bit 5 already gated in m3
    level(rev, imv, um[6], 2);
    level(rev, imv, um[7], 4);

    // store from m4 (coalesced: t[4:0] = lane)
#pragma unroll
    for (int k = 0; k < 8; k++) {
        int t = ((tid >> 5) << 8) | (k << 5) | (tid & 31);
        dst[base + (tbase | t)] = make_ulonglong2(rev[k], imv[k]);
    }
}

// ---------------------------------------------------------------------------
// Pass B: rotations qubits 0..4. Tile = j bits {14..11} + [6:0]; block id
// m = j[10:7]. j = ((t>>7)<<11) | (m<<7) | (t&0x7F).
// m1: t=(k<<8)|tid: reg bits t[10:8] = j{14,13,12} = qubits 1,2,3; + inlane q0.
// m2: t=((tid>>5)<<8)|(k<<5)|(tid&31): t[7]=j11=qubit 4 (s=4).
// NO CNOT relabels (deferred to next passA load / measurement parity).
// ---------------------------------------------------------------------------
__global__ void __launch_bounds__(THREADS, 4)
passB(const ulonglong2* __restrict__ src, ulonglong2* __restrict__ dst,
      const float* __restrict__ vp, int layer) {
    __shared__ ulonglong2 amp[PAD_SLOTS];
    __shared__ G7 um[4];
    __shared__ GL gl;
    int tid = threadIdx.x;
    int batch = blockIdx.x >> 4, m = blockIdx.x & 15;
    int base = batch << 15;

    if (tid < 4) { int q = (tid < 3) ? (3 - tid) : 4; make_g7(vp, layer, q, &um[tid]); }
    else if (tid == 4) make_gl(vp, layer, 0, &gl);
    __syncthreads();

    ull rev[8], imv[8];
#pragma unroll
    for (int k = 0; k < 8; k++) {
        int t = (k << 8) | tid;
        int j = ((t >> 7) << 11) | (m << 7) | (t & 0x7F);
        ulonglong2 v = src[base + j];
        rev[k] = v.x; imv[k] = v.y;
    }

    level(rev, imv, um[0], 1);   // qubit 3 (t8 = j12)
    level(rev, imv, um[1], 2);   // qubit 2 (t9 = j13)
    level(rev, imv, um[2], 4);   // qubit 1 (t10 = j14)
    inlane8(rev, imv, gl);       // qubit 0 (bit 15 = lane)

    // transpose m1 -> m2
#pragma unroll
    for (int k = 0; k < 8; k++) {
        int t = (k << 8) | tid;
        amp[t + (t >> 3)] = make_ulonglong2(rev[k], imv[k]);
    }
    __syncthreads();
#pragma unroll
    for (int k = 0; k < 8; k++) {
        int t = ((tid >> 5) << 8) | (k << 5) | (tid & 31);
        ulonglong2 v = amp[t + (t >> 3)];
        rev[k] = v.x; imv[k] = v.y;
    }

    level(rev, imv, um[3], 4);   // qubit 4 (t7 = j11)

#pragma unroll
    for (int k = 0; k < 8; k++) {
        int t = ((tid >> 5) << 8) | (k << 5) | (tid & 31);
        int j = ((t >> 7) << 11) | (m << 7) | (t & 0x7F);
        dst[base + j] = make_ulonglong2(rev[k], imv[k]);
    }
}

// ---------------------------------------------------------------------------
// Pass B measure: passB gates, then fold the final CNOT chain into the
// parity. Lane 1 (bit15 set) flips ALL 16 signs -> multiply by (1,-1) once.
// f over j (15 bits): f_k = parity(j >> k). Reduce, apply head.
// ---------------------------------------------------------------------------
__global__ void __launch_bounds__(THREADS, 3)
passBmeas(const ulonglong2* __restrict__ src, const float* __restrict__ vp,
          const float* __restrict__ hw, float* __restrict__ out, int layer) {
    __shared__ ulonglong2 amp[PAD_SLOTS];
    __shared__ G7 um[4];
    __shared__ GL gl;
    __shared__ float feats[16];
    int tid = threadIdx.x;
    int l = tid & 31;
    int batch = blockIdx.x >> 4, m = blockIdx.x & 15;
    int base = batch << 15;

    if (tid < 4) { int q = (tid < 3) ? (3 - tid) : 4; make_g7(vp, layer, q, &um[tid]); }
    else if (tid == 4) make_gl(vp, layer, 0, &gl);
    if (tid < 16) feats[tid] = 0.0f;
    __syncthreads();

    ull rev[8], imv[8];
#pragma unroll
    for (int k = 0; k < 8; k++) {
        int t = (k << 8) | tid;
        int j = ((t >> 7) << 11) | (m << 7) | (t & 0x7F);
        ulonglong2 v = src[base + j];
        rev[k] = v.x; imv[k] = v.y;
    }

    level(rev, imv, um[0], 1);
    level(rev, imv, um[1], 2);
    level(rev, imv, um[2], 4);
    inlane8(rev, imv, gl);

#pragma unroll
    for (int k = 0; k < 8; k++) {
        int t = (k << 8) | tid;
        amp[t + (t >> 3)] = make_ulonglong2(rev[k], imv[k]);
    }
    __syncthreads();
#pragma unroll
    for (int k = 0; k < 8; k++) {
        int t = ((tid >> 5) << 8) | (k << 5) | (tid & 31);
        ulonglong2 v = amp[t + (t >> 3)];
        rev[k] = v.x; imv[k] = v.y;
    }

    level(rev, imv, um[3], 4);

    // measurement
    const ull sgn = pk(1.0f, -1.0f);
    ull acc[16];
#pragma unroll
    for (int q = 0; q < 16; q++) acc[q] = pk(0.0f, 0.0f);
#pragma unroll
    for (int k = 0; k < 8; k++) {
        int t = ((tid >> 5) << 8) | (k << 5) | (tid & 31);
        int j = ((t >> 7) << 11) | (m << 7) | (t & 0x7F);
        ull p  = f2fma(rev[k], rev[k], f2mul(imv[k], imv[k]));
        ull pm = f2mul(p, sgn);              // lane1 sign flip (bit15 in every suffix)
        int f = j;                           // suffix-XOR parity over j bits
        f ^= f >> 1; f ^= f >> 2; f ^= f >> 4; f ^= f >> 8;
#pragma unroll
        for (int q = 0; q < 16; q++)
            acc[q] = ((f >> (15 - q)) & 1) ? f2sub(acc[q], pm) : f2add(acc[q], pm);
    }
    float accf[16];
#pragma unroll
    for (int q = 0; q < 16; q++) {
        float a0, a1; upk(acc[q], a0, a1);
        accf[q] = a0 + a1;                   // both lanes belong to this batch
#pragma unroll
        for (int off = 16; off; off >>= 1)
            accf[q] += __shfl_xor_sync(0xffffffffu, accf[q], off);
    }
    if (l == 0) {
#pragma unroll
        for (int q = 0; q < 16; q++) atomicAdd(&feats[q], accf[q]);
    }
    __syncthreads();
    if (tid == 0) {
        float v = 0.0f;
        for (int q = 0; q < 16; q++) v += feats[q] * hw[q];
        atomicAdd(&out[batch], v);
    }
}

__global__ void initOut(float* __restrict__ out, const float* __restrict__ hb) {
    if (threadIdx.x < 64) out[threadIdx.x] = hb[0];
}

extern "C" void kernel_launch(void* const* d_in, const int* in_sizes, int n_in,
                              void* d_out, int out_size) {
    const float* sr = (const float*)d_in[0];
    const float* si = (const float*)d_in[1];
    const float* vp = (const float*)d_in[2];
    const float* hw = (const float*)d_in[3];
    const float* hb = (const float*)d_in[4];
    float* out = (float*)d_out;

    ulonglong2 *b0, *b1;
    cudaGetSymbolAddress((void**)&b0, g_bufA);
    cudaGetSymbolAddress((void**)&b1, g_bufB);

    initOut<<<1, 64>>>(out, hb);
    // layer 0
    passA<<<1024, THREADS>>>(sr, si, nullptr, b0, vp, 0, 1);
    passB<<<1024, THREADS>>>(b0, b1, vp, 0);
    // layer 1 (load applies the FULL layer-0 CNOT chain q=0..14)
    passA<<<1024, THREADS>>>(nullptr, nullptr, b1, b0, vp, 1, 0);
    passB<<<1024, THREADS>>>(b0, b1, vp, 1);
    // layer 2
    passA<<<1024, THREADS>>>(nullptr, nullptr, b1, b0, vp, 2, 0);
    passBmeas<<<1024, THREADS>>>(b0, vp, hw, out, 2);
}

// round 12
// speedup vs baseline: 1.1147x; 1.0647x over previous
#include <cuda_runtime.h>
#include <cstdint>

// ============================================================================
// 16-qubit statevector simulator, 64 batches, 3 layers (Rot x16 + CNOT chain).
// Round 12: R11 bit-15 packing +
//  * CNOT(0,1) applied IN REGISTERS in passB (hi-lane exchange k <-> k^4);
//    deferred chain becomes q=1..14 (mask 0x3FFF, bit15-free) -> passA perm
//    load is a single 16B load per slot (no lane mixing).
//  * passB/passBmeas: ZERO smem amps / barriers. Slot bits = j[14:12]
//    (qubits 1..3), lane bit 4 = j11 (qubit 4 via one shfl level), qubit 0
//    in-lane. Loads/stores coalesced in 256B segments.
//  * initOut folded into passA layer 0.
// ============================================================================

#define THREADS   256
#define PAD_SLOTS (2048 + 256)    // slot = t + (t>>3), 16B elements

typedef unsigned long long ull;

__device__ ulonglong2 g_bufA[64 * 32768];
__device__ ulonglong2 g_bufB[64 * 32768];

struct G7 { ull ar, ai, nai, br, bi, nbr, nbi; };   // swap-free vgate coeffs
struct GL { ull p1, p2, p3, p4, q1, q2, q3, q4; };  // in-lane (bit15) coeffs

// ---------------- packed f32x2 primitives ----------------
__device__ __forceinline__ ull f2fma(ull a, ull b, ull c) {
    ull d; asm("fma.rn.f32x2 %0, %1, %2, %3;" : "=l"(d) : "l"(a), "l"(b), "l"(c));
    return d;
}
__device__ __forceinline__ ull f2mul(ull a, ull b) {
    ull d; asm("mul.rn.f32x2 %0, %1, %2;" : "=l"(d) : "l"(a), "l"(b));
    return d;
}
__device__ __forceinline__ ull f2add(ull a, ull b) {
    ull d; asm("add.rn.f32x2 %0, %1, %2;" : "=l"(d) : "l"(a), "l"(b));
    return d;
}
__device__ __forceinline__ ull f2sub(ull a, ull b) {
    ull d; asm("sub.rn.f32x2 %0, %1, %2;" : "=l"(d) : "l"(a), "l"(b));
    return d;
}
__device__ __forceinline__ ull pk(float lo, float hi) {
    ull r; asm("mov.b64 %0, {%1, %2};" : "=l"(r) : "f"(lo), "f"(hi));
    return r;
}
__device__ __forceinline__ void upk(ull v, float& lo, float& hi) {
    asm("mov.b64 {%0, %1}, %2;" : "=f"(lo), "=f"(hi) : "l"(v));
}
__device__ __forceinline__ ull swp(ull v) {
    float lo, hi; upk(v, lo, hi); return pk(hi, lo);
}

// row0 of U = Rz@Ry@Rx (SU(2)): u00 = (u0,u1), u01 = (u2,u3)
__device__ __forceinline__ void make_row(const float* __restrict__ vp, int layer, int q,
                                         float& u0, float& u1, float& u2, float& u3) {
    const float* p = vp + ((layer * 16) + q) * 6;
    float tx = p[0], ty = p[1], tz = p[2];
    float cx = cosf(0.5f * tx), sx = sinf(0.5f * tx);
    float cy = cosf(0.5f * ty), sy = sinf(0.5f * ty);
    float cz = cosf(0.5f * tz), sz = sinf(0.5f * tz);
    float m00r =  cy * cx, m00i =  sy * sx;
    float m01r = -sy * cx, m01i = -cy * sx;
    u0 = cz * m00r + sz * m00i; u1 = cz * m00i - sz * m00r;
    u2 = cz * m01r + sz * m01i; u3 = cz * m01i - sz * m01r;
}
__device__ __forceinline__ void make_g7(const float* vp, int layer, int q, G7* g) {
    float u0, u1, u2, u3; make_row(vp, layer, q, u0, u1, u2, u3);
    g->ar  = pk(u0, u0);  g->ai  = pk(u1, u1);  g->nai = pk(-u1, -u1);
    g->br  = pk(u2, u2);  g->bi  = pk(u3, u3);
    g->nbr = pk(-u2, -u2); g->nbi = pk(-u3, -u3);
}
// in-lane coeffs (lane0 = bit15 clear, lane1 = set) — verified R10
__device__ __forceinline__ void make_gl(const float* vp, int layer, int q, GL* g) {
    float u0, u1, u2, u3; make_row(vp, layer, q, u0, u1, u2, u3);
    g->p1 = pk(u0, u0);   g->p2 = pk(u2, -u2);
    g->p3 = pk(-u1, u1);  g->p4 = pk(-u3, -u3);
    g->q1 = pk(u1, -u1);  g->q2 = pk(u3, u3);
    g->q3 = pk(u0, u0);   g->q4 = pk(u2, -u2);
}

// swap-free SoA SU(2) gate on slot pair (a,b)
__device__ __forceinline__ void vgate(ull& rea, ull& ima, ull& reb, ull& imb,
                                      const G7& g) {
    ull nra = f2fma(g.ar,  rea, f2fma(g.nai, ima, f2fma(g.br,  reb, f2mul(g.nbi, imb))));
    ull nia = f2fma(g.ai,  rea, f2fma(g.ar,  ima, f2fma(g.bi,  reb, f2mul(g.br,  imb))));
    ull nrb = f2fma(g.nbr, rea, f2fma(g.nbi, ima, f2fma(g.ar,  reb, f2mul(g.ai,  imb))));
    ull nib = f2fma(g.bi,  rea, f2fma(g.nbr, ima, f2fma(g.nai, reb, f2mul(g.ar,  imb))));
    rea = nra; ima = nia; reb = nrb; imb = nib;
}

__device__ __forceinline__ void level(ull* __restrict__ rev, ull* __restrict__ imv,
                                      const G7& gsm, int s) {
    G7 g = gsm;
#pragma unroll
    for (int r0 = 0; r0 < 8; r0++) {
        if (r0 & s) continue;
        vgate(rev[r0], imv[r0], rev[r0 | s], imv[r0 | s], g);
    }
}

// in-lane gate across bit 15 (the packed lane)
__device__ __forceinline__ void inlane8(ull* __restrict__ rev, ull* __restrict__ imv,
                                        const GL& gsm) {
    GL g = gsm;
#pragma unroll
    for (int k = 0; k < 8; k++) {
        ull sR = swp(rev[k]), sI = swp(imv[k]);
        ull nR = f2fma(g.p1, rev[k], f2fma(g.p2, sR, f2fma(g.p3, imv[k], f2mul(g.p4, sI))));
        ull nI = f2fma(g.q1, rev[k], f2fma(g.q2, sR, f2fma(g.q3, imv[k], f2mul(g.q4, sI))));
        rev[k] = nR; imv[k] = nI;
    }
}

// ---------------------------------------------------------------------------
// Pass A: rotations qubits 5..15 (j bits [10:0]). Tile = j[10:0], tile id =
// j[14:11]; grid = batch(6b)<<4 | tile(4b). If !fromInput, the load applies
// the deferred chain q=1..14: a = j ^ ((j>>1) & 0x3FFF) — bit15-free, so one
// 16B load per slot, no lane mixing. Layer-0 variant also seeds out[]=hb[0].
// m1: t=(k<<8)|tid   m2: t=(tid<<3)|k   m3: t=((tid>>3)<<6)|(k<<3)|(tid&7)
// m4: t=((tid>>5)<<8)|(k<<5)|(tid&31).  um[b] = gate(qubit 15-b).
// ---------------------------------------------------------------------------
__global__ void __launch_bounds__(THREADS, 4)
passA(const float* __restrict__ sr, const float* __restrict__ si,
      const ulonglong2* __restrict__ src, ulonglong2* __restrict__ dst,
      const float* __restrict__ vp, float* __restrict__ out,
      const float* __restrict__ hb, int layer, int fromInput) {
    __shared__ ulonglong2 amp[PAD_SLOTS];
    __shared__ G7 um[11];
    int tid = threadIdx.x;
    int batch = blockIdx.x >> 4, tileid = blockIdx.x & 15;
    int base  = batch << 15;
    int tbase = tileid << 11;

    if (tid < 11) make_g7(vp, layer, 15 - tid, &um[tid]);
    __syncthreads();

    ull rev[8], imv[8];

    if (fromInput) {
        if (tid == 0 && blockIdx.x < 64) out[blockIdx.x] = hb[0];  // init output
        const float* srb = sr + (batch << 16);
        const float* sib = si + (batch << 16);
#pragma unroll
        for (int k = 0; k < 8; k++) {
            int j = tbase | (k << 8) | tid;
            rev[k] = pk(srb[j], srb[j | 0x8000]);
            imv[k] = pk(sib[j], sib[j | 0x8000]);
        }
    } else {
#pragma unroll
        for (int k = 0; k < 8; k++) {
            int j = tbase | (k << 8) | tid;
            int a = j ^ ((j >> 1) & 0x3FFF);       // chain q=1..14, lane-invariant
            ulonglong2 v = src[base + a];
            rev[k] = v.x; imv[k] = v.y;
        }
    }

    // m1: bits 8,9,10 (qubits 7,6,5)
    level(rev, imv, um[8], 1);
    level(rev, imv, um[9], 2);
    level(rev, imv, um[10], 4);

    // transpose m1 -> m2
#pragma unroll
    for (int k = 0; k < 8; k++) {
        int t = (k << 8) | tid;
        amp[t + (t >> 3)] = make_ulonglong2(rev[k], imv[k]);
    }
    __syncthreads();
#pragma unroll
    for (int k = 0; k < 8; k++) {
        int t = (tid << 3) | k;
        ulonglong2 v = amp[t + (t >> 3)];
        rev[k] = v.x; imv[k] = v.y;
    }

    // m2: bits 0,1,2 (qubits 15,14,13)
    level(rev, imv, um[0], 1);
    level(rev, imv, um[1], 2);
    level(rev, imv, um[2], 4);

    // transpose m2 -> m3
    __syncthreads();
#pragma unroll
    for (int k = 0; k < 8; k++) {
        int t = (tid << 3) | k;
        amp[t + (t >> 3)] = make_ulonglong2(rev[k], imv[k]);
    }
    __syncthreads();
#pragma unroll
    for (int k = 0; k < 8; k++) {
        int t = ((tid >> 3) << 6) | (k << 3) | (tid & 7);
        ulonglong2 v = amp[t + (t >> 3)];
        rev[k] = v.x; imv[k] = v.y;
    }

    // m3: bits 3,4,5 (qubits 12,11,10)
    level(rev, imv, um[3], 1);
    level(rev, imv, um[4], 2);
    level(rev, imv, um[5], 4);

    // transpose m3 -> m4
    __syncthreads();
#pragma unroll
    for (int k = 0; k < 8; k++) {
        int t = ((tid >> 3) << 6) | (k << 3) | (tid & 7);
        amp[t + (t >> 3)] = make_ulonglong2(rev[k], imv[k]);
    }
    __syncthreads();
#pragma unroll
    for (int k = 0; k < 8; k++) {
        int t = ((tid >> 5) << 8) | (k << 5) | (tid & 31);
        ulonglong2 v = amp[t + (t >> 3)];
        rev[k] = v.x; imv[k] = v.y;
    }

    // m4: bits 6,7 (qubits 9,8)
    level(rev, imv, um[6], 2);
    level(rev, imv, um[7], 4);

    // store from m4 (coalesced)
#pragma unroll
    for (int k = 0; k < 8; k++) {
        int t = ((tid >> 5) << 8) | (k << 5) | (tid & 31);
        dst[base + (tbase | t)] = make_ulonglong2(rev[k], imv[k]);
    }
}

// ---------------------------------------------------------------------------
// Pass B: qubits 0..4, ZERO smem amps / barriers (beyond coeff sync).
// Address mapping: j = (k<<12) | (tid4<<11) | (tid[7:5]<<8) | (m<<4) | tid[3:0]
//   slot bits k = j[14:12] = qubits 1..3 (vgate levels s=4,2,1)
//   lane bit 4 = j11 = qubit 4 (one shfl_xor(16) level)
//   packed lane = bit15 = qubit 0 (inlane)
// Then CNOT(0,1) in registers: lane1 hi-halves exchange between k and k^4.
// ---------------------------------------------------------------------------
__global__ void __launch_bounds__(THREADS, 4)
passB(const ulonglong2* __restrict__ src, ulonglong2* __restrict__ dst,
      const float* __restrict__ vp, int layer) {
    __shared__ G7 um[3];
    __shared__ GL gl;
    __shared__ float u4c[4];
    int tid = threadIdx.x;
    int batch = blockIdx.x >> 4, m = blockIdx.x & 15;
    int base = batch << 15;

    if (tid < 3) make_g7(vp, layer, 3 - tid, &um[tid]);   // um[0]=q3 um[1]=q2 um[2]=q1
    else if (tid == 3) make_gl(vp, layer, 0, &gl);
    else if (tid == 4) {
        float u0, u1, u2, u3; make_row(vp, layer, 4, u0, u1, u2, u3);
        u4c[0] = u0; u4c[1] = u1; u4c[2] = u2; u4c[3] = u3;
    }
    __syncthreads();

    int t4 = (tid >> 4) & 1;
    int jbase = (t4 << 11) | ((tid >> 5) << 8) | (m << 4) | (tid & 15);

    ull rev[8], imv[8];
#pragma unroll
    for (int k = 0; k < 8; k++) {
        ulonglong2 v = src[base + ((k << 12) | jbase)];
        rev[k] = v.x; imv[k] = v.y;
    }

    level(rev, imv, um[0], 1);   // qubit 3 (j12)
    level(rev, imv, um[1], 2);   // qubit 2 (j13)
    level(rev, imv, um[2], 4);   // qubit 1 (j14)

    // qubit 4 (j11 = lane bit 4) via shfl
    {
        float u0 = u4c[0], u1 = u4c[1], u2 = u4c[2], u3 = u4c[3];
        float b = t4 ? u1 : -u1;
        float c = t4 ? -u2 : u2;
        ull U0 = pk(u0, u0), U3 = pk(u3, u3), nU3 = pk(-u3, -u3);
        ull Bv = pk(b, b), nBv = pk(-b, -b), Cv = pk(c, c);
#pragma unroll
        for (int k = 0; k < 8; k++) {
            ull pre = __shfl_xor_sync(0xffffffffu, rev[k], 16);
            ull pim = __shfl_xor_sync(0xffffffffu, imv[k], 16);
            ull nre = f2fma(U0, rev[k], f2fma(Bv, imv[k], f2fma(Cv, pre, f2mul(nU3, pim))));
            ull nim = f2fma(nBv, rev[k], f2fma(U0, imv[k], f2fma(U3, pre, f2mul(Cv, pim))));
            rev[k] = nre; imv[k] = nim;
        }
    }

    inlane8(rev, imv, gl);       // qubit 0 (lane)

    // CNOT(0,1): new lane1 of slot k = old lane1 of slot k^4 (j14 flip)
#pragma unroll
    for (int k = 0; k < 4; k++) {
        float lo0, hi0, lo1, hi1;
        upk(rev[k], lo0, hi0); upk(rev[k | 4], lo1, hi1);
        rev[k] = pk(lo0, hi1); rev[k | 4] = pk(lo1, hi0);
        upk(imv[k], lo0, hi0); upk(imv[k | 4], lo1, hi1);
        imv[k] = pk(lo0, hi1); imv[k | 4] = pk(lo1, hi0);
    }

#pragma unroll
    for (int k = 0; k < 8; k++)
        dst[base + ((k << 12) | jbase)] = make_ulonglong2(rev[k], imv[k]);
}

// ---------------------------------------------------------------------------
// Pass B measure: same gates (no CNOT exchange); fold the ENTIRE final chain
// q=0..14 into the parity: f = suffix-XOR of j, lane1 flips all signs.
// ---------------------------------------------------------------------------
__global__ void __launch_bounds__(THREADS, 3)
passBmeas(const ulonglong2* __restrict__ src, const float* __restrict__ vp,
          const float* __restrict__ hw, float* __restrict__ out, int layer) {
    __shared__ G7 um[3];
    __shared__ GL gl;
    __shared__ float u4c[4];
    __shared__ float feats[16];
    int tid = threadIdx.x;
    int l = tid & 31;
    int batch = blockIdx.x >> 4, m = blockIdx.x & 15;
    int base = batch << 15;

    if (tid < 3) make_g7(vp, layer, 3 - tid, &um[tid]);
    else if (tid == 3) make_gl(vp, layer, 0, &gl);
    else if (tid == 4) {
        float u0, u1, u2, u3; make_row(vp, layer, 4, u0, u1, u2, u3);
        u4c[0] = u0; u4c[1] = u1; u4c[2] = u2; u4c[3] = u3;
    }
    if (tid < 16) feats[tid] = 0.0f;
    __syncthreads();

    int t4 = (tid >> 4) & 1;
    int jbase = (t4 << 11) | ((tid >> 5) << 8) | (m << 4) | (tid & 15);

    ull rev[8], imv[8];
#pragma unroll
    for (int k = 0; k < 8; k++) {
        ulonglong2 v = src[base + ((k << 12) | jbase)];
        rev[k] = v.x; imv[k] = v.y;
    }

    level(rev, imv, um[0], 1);
    level(rev, imv, um[1], 2);
    level(rev, imv, um[2], 4);
    {
        float u0 = u4c[0], u1 = u4c[1], u2 = u4c[2], u3 = u4c[3];
        float b = t4 ? u1 : -u1;
        float c = t4 ? -u2 : u2;
        ull U0 = pk(u0, u0), U3 = pk(u3, u3), nU3 = pk(-u3, -u3);
        ull Bv = pk(b, b), nBv = pk(-b, -b), Cv = pk(c, c);
#pragma unroll
        for (int k = 0; k < 8; k++) {
            ull pre = __shfl_xor_sync(0xffffffffu, rev[k], 16);
            ull pim = __shfl_xor_sync(0xffffffffu, imv[k], 16);
            ull nre = f2fma(U0, rev[k], f2fma(Bv, imv[k], f2fma(Cv, pre, f2mul(nU3, pim))));
            ull nim = f2fma(nBv, rev[k], f2fma(U0, imv[k], f2fma(U3, pre, f2mul(Cv, pim))));
            rev[k] = nre; imv[k] = nim;
        }
    }
    inlane8(rev, imv, gl);

    // measurement with full-chain parity
    const ull sgn = pk(1.0f, -1.0f);
    ull acc[16];
#pragma unroll
    for (int q = 0; q < 16; q++) acc[q] = pk(0.0f, 0.0f);
#pragma unroll
    for (int k = 0; k < 8; k++) {
        int j = (k << 12) | jbase;
        ull p  = f2fma(rev[k], rev[k], f2mul(imv[k], imv[k]));
        ull pm = f2mul(p, sgn);              // lane1 flips all signs (bit15)
        int f = j;                           // suffix-XOR parity over j bits
        f ^= f >> 1; f ^= f >> 2; f ^= f >> 4; f ^= f >> 8;
#pragma unroll
        for (int q = 0; q < 16; q++)
            acc[q] = ((f >> (15 - q)) & 1) ? f2sub(acc[q], pm) : f2add(acc[q], pm);
    }
    float accf[16];
#pragma unroll
    for (int q = 0; q < 16; q++) {
        float a0, a1; upk(acc[q], a0, a1);
        accf[q] = a0 + a1;
#pragma unroll
        for (int off = 16; off; off >>= 1)
            accf[q] += __shfl_xor_sync(0xffffffffu, accf[q], off);
    }
    if (l == 0) {
#pragma unroll
        for (int q = 0; q < 16; q++) atomicAdd(&feats[q], accf[q]);
    }
    __syncthreads();
    if (tid == 0) {
        float v = 0.0f;
        for (int q = 0; q < 16; q++) v += feats[q] * hw[q];
        atomicAdd(&out[batch], v);
    }
}

extern "C" void kernel_launch(void* const* d_in, const int* in_sizes, int n_in,
                              void* d_out, int out_size) {
    const float* sr = (const float*)d_in[0];
    const float* si = (const float*)d_in[1];
    const float* vp = (const float*)d_in[2];
    const float* hw = (const float*)d_in[3];
    const float* hb = (const float*)d_in[4];
    float* out = (float*)d_out;

    ulonglong2 *b0, *b1;
    cudaGetSymbolAddress((void**)&b0, g_bufA);
    cudaGetSymbolAddress((void**)&b1, g_bufB);

    // layer 0 (also seeds out[] = bias)
    passA<<<1024, THREADS>>>(sr, si, nullptr, b0, vp, out, hb, 0, 1);
    passB<<<1024, THREADS>>>(b0, b1, vp, 0);
    // layer 1 (load applies deferred chain q=1..14)
    passA<<<1024, THREADS>>>(nullptr, nullptr, b1, b0, vp, nullptr, nullptr, 1, 0);
    passB<<<1024, THREADS>>>(b0, b1, vp, 1);
    // layer 2
    passA<<<1024, THREADS>>>(nullptr, nullptr, b1, b0, vp, nullptr, nullptr, 2, 0);
    passBmeas<<<1024, THREADS>>>(b0, vp, hw, out, 2);
}